// round 2
// baseline (speedup 1.0000x reference)
#include <cuda_runtime.h>
#include <cuda_bf16.h>
#include <math.h>

#define BB 128
#define NN 256
#define EE 1024
#define DD 128
#define HH 8
#define DKK 16
#define DIN 130   // D + 2 degree features

// ---------------- scratch (device globals; no runtime allocation) ----------------
__device__ float g_deg_r[BB * NN];
__device__ float g_deg_c[BB * NN];
__device__ float g_q[BB * HH * NN * DKK];
__device__ float g_k[BB * HH * NN * DKK];
__device__ float g_v[BB * HH * NN * DKK];
__device__ float g_ef[BB * EE];
__device__ int   g_csr_ptr[BB * (NN + 1)];
__device__ int   g_csr_eid[BB * EE];
__device__ int   g_csr_col[BB * EE];
__device__ float g_wvec[DD];
__device__ float g_bmean;
__device__ float g_o[BB * NN * DD];
__device__ int   g_mask[BB * NN];
__device__ int   g_mflag;   // 0=uint8, 1=int32, 2=float32

// ---------------- packed f32x2 helpers (Blackwell FFMA2) ----------------
__device__ __forceinline__ unsigned long long fma2(unsigned long long a,
                                                   unsigned long long b,
                                                   unsigned long long c) {
    unsigned long long d;
    asm("fma.rn.f32x2 %0, %1, %2, %3;" : "=l"(d) : "l"(a), "l"(b), "l"(c));
    return d;
}
__device__ __forceinline__ unsigned long long mul2(unsigned long long a,
                                                   unsigned long long b) {
    unsigned long long d;
    asm("mul.rn.f32x2 %0, %1, %2;" : "=l"(d) : "l"(a), "l"(b));
    return d;
}
__device__ __forceinline__ unsigned long long pack2(float x, float y) {
    unsigned long long r;
    asm("mov.b64 %0, {%1, %2};" : "=l"(r) : "f"(x), "f"(y));
    return r;
}
__device__ __forceinline__ float2 unpack2(unsigned long long v) {
    float2 r;
    asm("mov.b64 {%0, %1}, %2;" : "=f"(r.x), "=f"(r.y) : "l"(v));
    return r;
}

// ---------------- kernel 0a: sniff mask dtype ----------------
// Reads the first 8192 32-bit words — safe for uint8 (32768B), int32, float32.
__global__ void k_mask_sniff(const unsigned int* __restrict__ mw) {
    __shared__ int c_f32, c_big;
    if (threadIdx.x == 0) { c_f32 = 0; c_big = 0; }
    __syncthreads();
    int nf = 0, nb = 0;
    for (int i = threadIdx.x; i < 8192; i += 256) {
        unsigned int w = mw[i];
        if (w == 0x3F800000u) nf++;
        else if (w > 1u) nb++;
    }
    atomicAdd(&c_f32, nf);
    atomicAdd(&c_big, nb);
    __syncthreads();
    if (threadIdx.x == 0) {
        int flag;
        if (c_f32 > 64) flag = 2;       // float32
        else if (c_big > 64) flag = 0;  // packed uint8 bytes
        else flag = 1;                  // int32 0/1
        g_mflag = flag;
    }
}

// ---------------- kernel 0b: normalize mask to int ----------------
__global__ void k_mask_conv(const void* __restrict__ mp) {
    int i = blockIdx.x * 256 + threadIdx.x;   // B*N threads
    int f = g_mflag;
    int v;
    if (f == 2)      v = (reinterpret_cast<const float*>(mp)[i] != 0.0f);
    else if (f == 1) v = (reinterpret_cast<const int*>(mp)[i] != 0);
    else             v = (reinterpret_cast<const unsigned char*>(mp)[i] != 0);
    g_mask[i] = v;
}

// ---------------- kernel 1: row-mean of We_w, mean of We_b ----------------
__global__ void k_wvec(const float* __restrict__ Wew, const float* __restrict__ Web) {
    int i = threadIdx.x;  // 128 threads
    float s = 0.f;
    for (int j = 0; j < DD; j++) s += Wew[i * DD + j];
    g_wvec[i] = s * (1.0f / DD);
    if (i == 0) {
        float b = 0.f;
        for (int j = 0; j < DD; j++) b += Web[j];
        g_bmean = b * (1.0f / DD);
    }
}

// ---------------- kernel 2: degrees + per-batch CSR over row indices ----------------
__global__ void k_deg_csr(const int* __restrict__ ei) {
    int b = blockIdx.x, t = threadIdx.x;  // 256 threads
    __shared__ int hr[NN], hc[NN], sc[NN], off[NN];
    hr[t] = 0; hc[t] = 0;
    __syncthreads();
    const int* rows = ei + b * 2 * EE;
    const int* cols = rows + EE;
    for (int e = t; e < EE; e += 256) {
        atomicAdd(&hr[rows[e]], 1);
        atomicAdd(&hc[cols[e]], 1);
    }
    __syncthreads();
    g_deg_r[b * NN + t] = (float)hr[t];
    g_deg_c[b * NN + t] = (float)hc[t];
    sc[t] = hr[t];
    __syncthreads();
    // Hillis-Steele inclusive scan over 256 counts
    for (int d = 1; d < NN; d <<= 1) {
        int v = (t >= d) ? sc[t - d] : 0;
        __syncthreads();
        sc[t] += v;
        __syncthreads();
    }
    if (t == 0) g_csr_ptr[b * (NN + 1)] = 0;
    g_csr_ptr[b * (NN + 1) + t + 1] = sc[t];
    off[t] = sc[t] - hr[t];
    __syncthreads();
    for (int e = t; e < EE; e += 256) {
        int r = rows[e];
        int pos = atomicAdd(&off[r], 1);
        g_csr_eid[b * EE + pos] = e;
        g_csr_col[b * EE + pos] = cols[e];
    }
}

// ---------------- kernel 3: edge features (dot with w_vec) ----------------
__global__ void k_ef(const float* __restrict__ ea) {
    int warp = threadIdx.x >> 5, lane = threadIdx.x & 31;
    int e = blockIdx.x * 8 + warp;  // global edge id in [0, B*E)
    const float* row = ea + (size_t)e * DD;
    float4 a = *reinterpret_cast<const float4*>(row + lane * 4);
    float4 w = *reinterpret_cast<const float4*>(g_wvec + lane * 4);
    float d = a.x * w.x + a.y * w.y + a.z * w.z + a.w * w.w;
    #pragma unroll
    for (int o = 16; o; o >>= 1) d += __shfl_xor_sync(0xFFFFFFFFu, d, o);
    if (lane == 0) g_ef[e] = d + g_bmean;
}

// ---------------- kernel 4: QKV projection (x_new @ W), W in shared ----------------
// grid (512, 3), block 256. 8 warps x 8 rows each = 64 rows/block.
__global__ void k_qkv(const float* __restrict__ x,
                      const float* __restrict__ Wq,
                      const float* __restrict__ Wk,
                      const float* __restrict__ Wv) {
    extern __shared__ float Ws[];  // DIN*DD floats = 66560 B
    const float* W = (blockIdx.y == 0) ? Wq : (blockIdx.y == 1) ? Wk : Wv;
    float* out = (blockIdx.y == 0) ? g_q : (blockIdx.y == 1) ? g_k : g_v;
    int t = threadIdx.x;
    for (int i = t; i < DIN * DD; i += 256) Ws[i] = W[i];
    __syncthreads();
    int warp = t >> 5, lane = t & 31;
    int c0 = lane * 4;
    int h = c0 >> 4, dk = c0 & 15;
    #pragma unroll 1
    for (int i = 0; i < 8; i++) {
        int row = blockIdx.x * 64 + warp * 8 + i;
        int b = row >> 8, n = row & 255;
        const float* xr = x + (size_t)row * DD;
        unsigned long long acc0 = 0ull, acc1 = 0ull;
        for (int kk = 0; kk < DD; kk += 4) {
            float4 a = *reinterpret_cast<const float4*>(xr + kk);
            float av[4] = {a.x, a.y, a.z, a.w};
            #pragma unroll
            for (int j = 0; j < 4; j++) {
                unsigned long long a2 = pack2(av[j], av[j]);
                ulonglong2 w = *reinterpret_cast<const ulonglong2*>(Ws + (kk + j) * DD + c0);
                acc0 = fma2(a2, w.x, acc0);
                acc1 = fma2(a2, w.y, acc1);
            }
        }
        {   // degree features
            float dr = g_deg_r[row];
            unsigned long long a2 = pack2(dr, dr);
            ulonglong2 w = *reinterpret_cast<const ulonglong2*>(Ws + 128 * DD + c0);
            acc0 = fma2(a2, w.x, acc0);
            acc1 = fma2(a2, w.y, acc1);
            float dc = g_deg_c[row];
            a2 = pack2(dc, dc);
            w = *reinterpret_cast<const ulonglong2*>(Ws + 129 * DD + c0);
            acc0 = fma2(a2, w.x, acc0);
            acc1 = fma2(a2, w.y, acc1);
        }
        float2 p0 = unpack2(acc0), p1 = unpack2(acc1);
        float4 o = make_float4(p0.x, p0.y, p1.x, p1.y);
        *reinterpret_cast<float4*>(out + ((size_t)(b * HH + h) * NN + n) * DKK + dk) = o;
    }
}

// ---------------- kernel 5: attention per (b,h), online softmax + sparse bias ----------------
__global__ void k_attn() {
    int bh = blockIdx.x;           // b*H + h
    int b = bh >> 3, h = bh & 7;
    int t = threadIdx.x;           // 256 threads = one query each
    __shared__ __align__(16) float sk[NN * DKK];
    __shared__ __align__(16) float sv[NN * DKK];
    __shared__ int sm[NN];
    const float* kg = g_k + (size_t)bh * NN * DKK;
    const float* vg = g_v + (size_t)bh * NN * DKK;
    for (int i = t; i < NN * DKK / 4; i += 256) {
        reinterpret_cast<float4*>(sk)[i] = reinterpret_cast<const float4*>(kg)[i];
        reinterpret_cast<float4*>(sv)[i] = reinterpret_cast<const float4*>(vg)[i];
    }
    sm[t] = g_mask[b * NN + t];
    __syncthreads();

    // load my query (16 floats) into 8 packed pairs
    const float* qg = g_q + ((size_t)bh * NN + t) * DKK;
    unsigned long long q2[8];
    #pragma unroll
    for (int i = 0; i < 4; i++) {
        float4 qv = reinterpret_cast<const float4*>(qg)[i];
        q2[2 * i]     = pack2(qv.x, qv.y);
        q2[2 * i + 1] = pack2(qv.z, qv.w);
    }

    float m = -1e30f, l = 0.f;
    unsigned long long o2[8];
    #pragma unroll
    for (int i = 0; i < 8; i++) o2[i] = 0ull;

    for (int j = 0; j < NN; j++) {
        if (!sm[j]) continue;  // uniform across block
        const ulonglong2* kp = reinterpret_cast<const ulonglong2*>(sk + j * DKK);
        ulonglong2 kA = kp[0], kB = kp[1];
        unsigned long long acc = 0ull;
        acc = fma2(q2[0], kA.x, acc);
        acc = fma2(q2[1], kA.y, acc);
        acc = fma2(q2[2], kB.x, acc);
        acc = fma2(q2[3], kB.y, acc);
        kA = kp[2]; kB = kp[3];
        acc = fma2(q2[4], kA.x, acc);
        acc = fma2(q2[5], kA.y, acc);
        acc = fma2(q2[6], kB.x, acc);
        acc = fma2(q2[7], kB.y, acc);
        float2 hh = unpack2(acc);
        float s = (hh.x + hh.y) * 0.25f;  // 1/sqrt(16)

        if (s > m) {
            float corr = __expf(m - s);
            unsigned long long c2 = pack2(corr, corr);
            l *= corr;
            #pragma unroll
            for (int i = 0; i < 8; i++) o2[i] = mul2(c2, o2[i]);
            m = s;
        }
        float p = __expf(s - m);
        l += p;
        unsigned long long p2 = pack2(p, p);
        const ulonglong2* vp = reinterpret_cast<const ulonglong2*>(sv + j * DKK);
        ulonglong2 vA = vp[0], vB = vp[1];
        o2[0] = fma2(p2, vA.x, o2[0]);
        o2[1] = fma2(p2, vA.y, o2[1]);
        o2[2] = fma2(p2, vB.x, o2[2]);
        o2[3] = fma2(p2, vB.y, o2[3]);
        vA = vp[2]; vB = vp[3];
        o2[4] = fma2(p2, vA.x, o2[4]);
        o2[5] = fma2(p2, vA.y, o2[5]);
        o2[6] = fma2(p2, vB.x, o2[6]);
        o2[7] = fma2(p2, vB.y, o2[7]);
    }

    // sparse edge-bias correction: exp(s+f) = exp(s) + exp(s)*expm1(f)
    int base = b * EE;
    int p0 = g_csr_ptr[b * (NN + 1) + t];
    int p1 = g_csr_ptr[b * (NN + 1) + t + 1];
    for (int idx = p0; idx < p1; idx++) {
        int c = g_csr_col[base + idx];
        if (!sm[c]) continue;   // masked -> contribution is exactly 0
        float f = g_ef[base + g_csr_eid[base + idx]];
        const ulonglong2* kp = reinterpret_cast<const ulonglong2*>(sk + c * DKK);
        ulonglong2 kA = kp[0], kB = kp[1];
        unsigned long long acc = 0ull;
        acc = fma2(q2[0], kA.x, acc);
        acc = fma2(q2[1], kA.y, acc);
        acc = fma2(q2[2], kB.x, acc);
        acc = fma2(q2[3], kB.y, acc);
        kA = kp[2]; kB = kp[3];
        acc = fma2(q2[4], kA.x, acc);
        acc = fma2(q2[5], kA.y, acc);
        acc = fma2(q2[6], kB.x, acc);
        acc = fma2(q2[7], kB.y, acc);
        float2 hh = unpack2(acc);
        float s = (hh.x + hh.y) * 0.25f;
        float w = __expf(s - m) * expm1f(f);
        l += w;
        unsigned long long w2 = pack2(w, w);
        const ulonglong2* vp = reinterpret_cast<const ulonglong2*>(sv + c * DKK);
        ulonglong2 vA = vp[0], vB = vp[1];
        o2[0] = fma2(w2, vA.x, o2[0]);
        o2[1] = fma2(w2, vA.y, o2[1]);
        o2[2] = fma2(w2, vB.x, o2[2]);
        o2[3] = fma2(w2, vB.y, o2[3]);
        vA = vp[2]; vB = vp[3];
        o2[4] = fma2(w2, vA.x, o2[4]);
        o2[5] = fma2(w2, vA.y, o2[5]);
        o2[6] = fma2(w2, vB.x, o2[6]);
        o2[7] = fma2(w2, vB.y, o2[7]);
    }

    float inv = 1.0f / l;
    float* og = g_o + ((size_t)(b * NN + t)) * DD + h * DKK;
    #pragma unroll
    for (int i = 0; i < 4; i++) {
        float2 e0 = unpack2(o2[2 * i]);
        float2 e1 = unpack2(o2[2 * i + 1]);
        float4 o = make_float4(e0.x * inv, e0.y * inv, e1.x * inv, e1.y * inv);
        reinterpret_cast<float4*>(og)[i] = o;
    }
}

// ---------------- kernel 6: residual + layernorm ----------------
__global__ void k_ln(const float* __restrict__ x,
                     const float* __restrict__ lg,
                     const float* __restrict__ lb,
                     float* __restrict__ out) {
    int warp = threadIdx.x >> 5, lane = threadIdx.x & 31;
    int row = blockIdx.x * 8 + warp;
    int c0 = lane * 4;
    float4 o = *reinterpret_cast<const float4*>(g_o + (size_t)row * DD + c0);
    float4 xv = *reinterpret_cast<const float4*>(x + (size_t)row * DD + c0);
    float4 s = make_float4(o.x + xv.x, o.y + xv.y, o.z + xv.z, o.w + xv.w);
    float sum = s.x + s.y + s.z + s.w;
    float sq  = s.x * s.x + s.y * s.y + s.z * s.z + s.w * s.w;
    #pragma unroll
    for (int off = 16; off; off >>= 1) {
        sum += __shfl_xor_sync(0xFFFFFFFFu, sum, off);
        sq  += __shfl_xor_sync(0xFFFFFFFFu, sq, off);
    }
    float mu = sum * (1.0f / DD);
    float var = sq * (1.0f / DD) - mu * mu;
    float rstd = rsqrtf(var + 1e-6f);
    float4 g = *reinterpret_cast<const float4*>(lg + c0);
    float4 be = *reinterpret_cast<const float4*>(lb + c0);
    float4 r;
    r.x = (s.x - mu) * rstd * g.x + be.x;
    r.y = (s.y - mu) * rstd * g.y + be.y;
    r.z = (s.z - mu) * rstd * g.z + be.z;
    r.w = (s.w - mu) * rstd * g.w + be.w;
    *reinterpret_cast<float4*>(out + (size_t)row * DD + c0) = r;
}

// ---------------- launch ----------------
extern "C" void kernel_launch(void* const* d_in, const int* in_sizes, int n_in,
                              void* d_out, int out_size) {
    const float* x    = (const float*)d_in[0];
    const void*  mask = d_in[1];
    const int*   ei   = (const int*)d_in[2];
    const float* ea   = (const float*)d_in[3];
    const float* Wq   = (const float*)d_in[4];
    const float* Wk   = (const float*)d_in[5];
    const float* Wv   = (const float*)d_in[6];
    const float* Wew  = (const float*)d_in[7];
    const float* Web  = (const float*)d_in[8];
    const float* lg   = (const float*)d_in[9];
    const float* lb   = (const float*)d_in[10];
    float* out = (float*)d_out;

    k_mask_sniff<<<1, 256>>>((const unsigned int*)mask);
    k_mask_conv<<<(BB * NN) / 256, 256>>>(mask);
    k_wvec<<<1, 128>>>(Wew, Web);
    k_deg_csr<<<BB, 256>>>(ei);
    k_ef<<<(BB * EE) / 8, 256>>>(ea);

    cudaFuncSetAttribute(k_qkv, cudaFuncAttributeMaxDynamicSharedMemorySize,
                         DIN * DD * (int)sizeof(float));
    k_qkv<<<dim3((BB * NN) / 64, 3), 256, DIN * DD * sizeof(float)>>>(x, Wq, Wk, Wv);

    k_attn<<<BB * HH, 256>>>();
    k_ln<<<(BB * NN) / 8, 256>>>(x, lg, lb, out);
}

// round 3
// speedup vs baseline: 1.3971x; 1.3971x over previous
#include <cuda_runtime.h>
#include <cuda_bf16.h>
#include <math.h>

#define BB 128
#define NN 256
#define EE 1024
#define DD 128
#define HH 8
#define DKK 16
#define DIN 130   // D + 2 degree features

// ---------------- scratch (device globals; no runtime allocation) ----------------
__device__ float g_deg_r[BB * NN];
__device__ float g_deg_c[BB * NN];
__device__ float g_q[BB * HH * NN * DKK];
__device__ float g_k[BB * HH * NN * DKK];
__device__ float g_v[BB * HH * NN * DKK];
__device__ float g_ef[BB * EE];
__device__ int   g_csr_ptr[BB * (NN + 1)];
__device__ int   g_csr_eid[BB * EE];
__device__ int   g_csr_col[BB * EE];
__device__ float g_wvec[DD];
__device__ float g_bmean;
__device__ float g_o[BB * NN * DD];
__device__ int   g_mask[BB * NN];
__device__ int   g_mflag;          // 0=uint8, 1=int32, 2=float32
__device__ int   g_klist[BB * NN]; // compacted active-key indices per batch
__device__ int   g_kcnt[BB];

// ---------------- packed f32x2 helpers (Blackwell FFMA2) ----------------
__device__ __forceinline__ unsigned long long fma2(unsigned long long a,
                                                   unsigned long long b,
                                                   unsigned long long c) {
    unsigned long long d;
    asm("fma.rn.f32x2 %0, %1, %2, %3;" : "=l"(d) : "l"(a), "l"(b), "l"(c));
    return d;
}
__device__ __forceinline__ unsigned long long pack2(float x, float y) {
    unsigned long long r;
    asm("mov.b64 %0, {%1, %2};" : "=l"(r) : "f"(x), "f"(y));
    return r;
}
__device__ __forceinline__ float2 unpack2(unsigned long long v) {
    float2 r;
    asm("mov.b64 {%0, %1}, %2;" : "=f"(r.x), "=f"(r.y) : "l"(v));
    return r;
}

// ---------------- kernel 0a: sniff mask dtype ----------------
__global__ void k_mask_sniff(const unsigned int* __restrict__ mw) {
    __shared__ int c_f32, c_big;
    if (threadIdx.x == 0) { c_f32 = 0; c_big = 0; }
    __syncthreads();
    int nf = 0, nb = 0;
    for (int i = threadIdx.x; i < 8192; i += 256) {
        unsigned int w = mw[i];
        if (w == 0x3F800000u) nf++;
        else if (w > 1u) nb++;
    }
    atomicAdd(&c_f32, nf);
    atomicAdd(&c_big, nb);
    __syncthreads();
    if (threadIdx.x == 0) {
        int flag;
        if (c_f32 > 64) flag = 2;
        else if (c_big > 64) flag = 0;
        else flag = 1;
        g_mflag = flag;
    }
}

// ---------------- kernel 0b: normalize mask to int ----------------
__global__ void k_mask_conv(const void* __restrict__ mp) {
    int i = blockIdx.x * 256 + threadIdx.x;
    int f = g_mflag;
    int v;
    if (f == 2)      v = (reinterpret_cast<const float*>(mp)[i] != 0.0f);
    else if (f == 1) v = (reinterpret_cast<const int*>(mp)[i] != 0);
    else             v = (reinterpret_cast<const unsigned char*>(mp)[i] != 0);
    g_mask[i] = v;
}

// ---------------- kernel 1: row-mean of We_w, mean of We_b ----------------
__global__ void k_wvec(const float* __restrict__ Wew, const float* __restrict__ Web) {
    int i = threadIdx.x;  // 128 threads
    float s = 0.f;
    for (int j = 0; j < DD; j++) s += Wew[i * DD + j];
    g_wvec[i] = s * (1.0f / DD);
    if (i == 0) {
        float b = 0.f;
        for (int j = 0; j < DD; j++) b += Web[j];
        g_bmean = b * (1.0f / DD);
    }
}

// ---------------- kernel 2: degrees + CSR + compacted key list ----------------
__global__ void k_deg_csr(const int* __restrict__ ei) {
    int b = blockIdx.x, t = threadIdx.x;  // 256 threads
    __shared__ int hr[NN], hc[NN], sc[NN], off[NN];
    hr[t] = 0; hc[t] = 0;
    __syncthreads();
    const int* rows = ei + b * 2 * EE;
    const int* cols = rows + EE;
    for (int e = t; e < EE; e += 256) {
        atomicAdd(&hr[rows[e]], 1);
        atomicAdd(&hc[cols[e]], 1);
    }
    __syncthreads();
    g_deg_r[b * NN + t] = (float)hr[t];
    g_deg_c[b * NN + t] = (float)hc[t];
    sc[t] = hr[t];
    __syncthreads();
    for (int d = 1; d < NN; d <<= 1) {
        int v = (t >= d) ? sc[t - d] : 0;
        __syncthreads();
        sc[t] += v;
        __syncthreads();
    }
    if (t == 0) g_csr_ptr[b * (NN + 1)] = 0;
    g_csr_ptr[b * (NN + 1) + t + 1] = sc[t];
    off[t] = sc[t] - hr[t];
    __syncthreads();
    for (int e = t; e < EE; e += 256) {
        int r = rows[e];
        int pos = atomicAdd(&off[r], 1);
        g_csr_eid[b * EE + pos] = e;
        g_csr_col[b * EE + pos] = cols[e];
    }
    // compacted active-key list (deterministic: in-order scan of mask)
    __syncthreads();
    int mv = g_mask[b * NN + t];
    sc[t] = mv;
    __syncthreads();
    for (int d = 1; d < NN; d <<= 1) {
        int v = (t >= d) ? sc[t - d] : 0;
        __syncthreads();
        sc[t] += v;
        __syncthreads();
    }
    if (mv) g_klist[b * NN + sc[t] - 1] = t;
    if (t == NN - 1) g_kcnt[b] = sc[t];
}

// ---------------- kernel 3: edge features (dot with w_vec) ----------------
__global__ void k_ef(const float* __restrict__ ea) {
    int warp = threadIdx.x >> 5, lane = threadIdx.x & 31;
    int e = blockIdx.x * 8 + warp;
    const float* row = ea + (size_t)e * DD;
    float4 a = *reinterpret_cast<const float4*>(row + lane * 4);
    float4 w = *reinterpret_cast<const float4*>(g_wvec + lane * 4);
    float d = a.x * w.x + a.y * w.y + a.z * w.z + a.w * w.w;
    #pragma unroll
    for (int o = 16; o; o >>= 1) d += __shfl_xor_sync(0xFFFFFFFFu, d, o);
    if (lane == 0) g_ef[e] = d + g_bmean;
}

// ---------------- kernel 4: QKV projection, 8-row register tiling ----------------
// grid (512, 3), block 256. Warp handles 8 rows; one W LDS serves 8 rows x 4 cols.
__global__ void k_qkv(const float* __restrict__ x,
                      const float* __restrict__ Wq,
                      const float* __restrict__ Wk,
                      const float* __restrict__ Wv) {
    extern __shared__ float Ws[];  // DIN*DD floats
    const float* W = (blockIdx.y == 0) ? Wq : (blockIdx.y == 1) ? Wk : Wv;
    float* out = (blockIdx.y == 0) ? g_q : (blockIdx.y == 1) ? g_k : g_v;
    int t = threadIdx.x;
    for (int i = t; i < DIN * DD; i += 256) Ws[i] = W[i];
    __syncthreads();
    int warp = t >> 5, lane = t & 31;
    int c0 = lane * 4;
    int r0 = blockIdx.x * 64 + warp * 8;

    unsigned long long acc[8][2];
    #pragma unroll
    for (int i = 0; i < 8; i++) { acc[i][0] = 0ull; acc[i][1] = 0ull; }

    #pragma unroll 4
    for (int kc = 0; kc < DD; kc += 4) {
        float4 xb[8];
        #pragma unroll
        for (int i = 0; i < 8; i++)
            xb[i] = *reinterpret_cast<const float4*>(x + (size_t)(r0 + i) * DD + kc);
        #pragma unroll
        for (int j = 0; j < 4; j++) {
            ulonglong2 w = *reinterpret_cast<const ulonglong2*>(Ws + (kc + j) * DD + c0);
            #pragma unroll
            for (int i = 0; i < 8; i++) {
                float xv = (j == 0) ? xb[i].x : (j == 1) ? xb[i].y : (j == 2) ? xb[i].z : xb[i].w;
                unsigned long long a2 = pack2(xv, xv);
                acc[i][0] = fma2(a2, w.x, acc[i][0]);
                acc[i][1] = fma2(a2, w.y, acc[i][1]);
            }
        }
    }
    {   // degree features (rows 128,129 of W)
        ulonglong2 w0 = *reinterpret_cast<const ulonglong2*>(Ws + 128 * DD + c0);
        ulonglong2 w1 = *reinterpret_cast<const ulonglong2*>(Ws + 129 * DD + c0);
        #pragma unroll
        for (int i = 0; i < 8; i++) {
            float dr = g_deg_r[r0 + i];
            unsigned long long a2 = pack2(dr, dr);
            acc[i][0] = fma2(a2, w0.x, acc[i][0]);
            acc[i][1] = fma2(a2, w0.y, acc[i][1]);
            float dc = g_deg_c[r0 + i];
            a2 = pack2(dc, dc);
            acc[i][0] = fma2(a2, w1.x, acc[i][0]);
            acc[i][1] = fma2(a2, w1.y, acc[i][1]);
        }
    }
    int h = c0 >> 4, dk = c0 & 15;
    #pragma unroll
    for (int i = 0; i < 8; i++) {
        int row = r0 + i;
        int b = row >> 8, n = row & 255;
        float2 p0 = unpack2(acc[i][0]), p1 = unpack2(acc[i][1]);
        float4 o = make_float4(p0.x, p0.y, p1.x, p1.y);
        *reinterpret_cast<float4*>(out + ((size_t)(b * HH + h) * NN + n) * DKK + dk) = o;
    }
}

// ---------------- kernel 5: attention, branch-free, no-max softmax, 2 q/thread ----------------
__global__ void __launch_bounds__(128) k_attn() {
    int bh = blockIdx.x;           // b*H + h
    int b = bh >> 3, h = bh & 7;
    int t = threadIdx.x;           // 128 threads, queries t and t+128
    __shared__ __align__(16) float sk[NN * DKK];
    __shared__ __align__(16) float sv[NN * DKK];
    __shared__ int slist[NN];
    __shared__ int sm[NN];
    __shared__ int scnt;
    const float4* kg = reinterpret_cast<const float4*>(g_k + (size_t)bh * NN * DKK);
    const float4* vg = reinterpret_cast<const float4*>(g_v + (size_t)bh * NN * DKK);
    float4* sk4 = reinterpret_cast<float4*>(sk);
    float4* sv4 = reinterpret_cast<float4*>(sv);
    #pragma unroll
    for (int i = 0; i < 8; i++) {
        sk4[t + i * 128] = kg[t + i * 128];
        sv4[t + i * 128] = vg[t + i * 128];
    }
    sm[t] = g_mask[b * NN + t];
    sm[t + 128] = g_mask[b * NN + t + 128];
    slist[t] = g_klist[b * NN + t];
    slist[t + 128] = g_klist[b * NN + t + 128];
    if (t == 0) scnt = g_kcnt[b];
    __syncthreads();

    // queries t and t+128
    unsigned long long qA[8], qB[8];
    {
        const float4* qg = reinterpret_cast<const float4*>(g_q + ((size_t)bh * NN + t) * DKK);
        #pragma unroll
        for (int i = 0; i < 4; i++) {
            float4 qv = qg[i];
            qA[2 * i]     = pack2(qv.x, qv.y);
            qA[2 * i + 1] = pack2(qv.z, qv.w);
        }
        qg = reinterpret_cast<const float4*>(g_q + ((size_t)bh * NN + t + 128) * DKK);
        #pragma unroll
        for (int i = 0; i < 4; i++) {
            float4 qv = qg[i];
            qB[2 * i]     = pack2(qv.x, qv.y);
            qB[2 * i + 1] = pack2(qv.z, qv.w);
        }
    }

    float lA = 0.f, lB = 0.f;
    unsigned long long oA[8], oB[8];
    #pragma unroll
    for (int i = 0; i < 8; i++) { oA[i] = 0ull; oB[i] = 0ull; }

    int cnt = scnt;
    for (int jj = 0; jj < cnt; jj++) {
        int j = slist[jj];
        const ulonglong2* kp = reinterpret_cast<const ulonglong2*>(sk + j * DKK);
        ulonglong2 k0 = kp[0], k1 = kp[1], k2 = kp[2], k3 = kp[3];
        unsigned long long aA = 0ull, aB = 0ull;
        aA = fma2(qA[0], k0.x, aA);  aB = fma2(qB[0], k0.x, aB);
        aA = fma2(qA[1], k0.y, aA);  aB = fma2(qB[1], k0.y, aB);
        aA = fma2(qA[2], k1.x, aA);  aB = fma2(qB[2], k1.x, aB);
        aA = fma2(qA[3], k1.y, aA);  aB = fma2(qB[3], k1.y, aB);
        aA = fma2(qA[4], k2.x, aA);  aB = fma2(qB[4], k2.x, aB);
        aA = fma2(qA[5], k2.y, aA);  aB = fma2(qB[5], k2.y, aB);
        aA = fma2(qA[6], k3.x, aA);  aB = fma2(qB[6], k3.x, aB);
        aA = fma2(qA[7], k3.y, aA);  aB = fma2(qB[7], k3.y, aB);
        float2 hA = unpack2(aA), hB = unpack2(aB);
        float pA = __expf((hA.x + hA.y) * 0.25f);
        float pB = __expf((hB.x + hB.y) * 0.25f);
        lA += pA;  lB += pB;
        unsigned long long p2A = pack2(pA, pA);
        unsigned long long p2B = pack2(pB, pB);
        const ulonglong2* vp = reinterpret_cast<const ulonglong2*>(sv + j * DKK);
        ulonglong2 v0 = vp[0], v1 = vp[1], v2 = vp[2], v3 = vp[3];
        oA[0] = fma2(p2A, v0.x, oA[0]);  oB[0] = fma2(p2B, v0.x, oB[0]);
        oA[1] = fma2(p2A, v0.y, oA[1]);  oB[1] = fma2(p2B, v0.y, oB[1]);
        oA[2] = fma2(p2A, v1.x, oA[2]);  oB[2] = fma2(p2B, v1.x, oB[2]);
        oA[3] = fma2(p2A, v1.y, oA[3]);  oB[3] = fma2(p2B, v1.y, oB[3]);
        oA[4] = fma2(p2A, v2.x, oA[4]);  oB[4] = fma2(p2B, v2.x, oB[4]);
        oA[5] = fma2(p2A, v2.y, oA[5]);  oB[5] = fma2(p2B, v2.y, oB[5]);
        oA[6] = fma2(p2A, v3.x, oA[6]);  oB[6] = fma2(p2B, v3.x, oB[6]);
        oA[7] = fma2(p2A, v3.y, oA[7]);  oB[7] = fma2(p2B, v3.y, oB[7]);
    }

    // sparse edge-bias correction: exp(s+f) = exp(s) + exp(s)*expm1(f)
    int base = b * EE;
    #pragma unroll
    for (int qi = 0; qi < 2; qi++) {
        int q = t + qi * 128;
        const unsigned long long* qq = qi ? qB : qA;
        unsigned long long* oo = qi ? oB : oA;
        float* ll = qi ? &lB : &lA;
        int p0 = g_csr_ptr[b * (NN + 1) + q];
        int p1 = g_csr_ptr[b * (NN + 1) + q + 1];
        for (int idx = p0; idx < p1; idx++) {
            int c = g_csr_col[base + idx];
            if (!sm[c]) continue;
            float f = g_ef[base + g_csr_eid[base + idx]];
            const ulonglong2* kp = reinterpret_cast<const ulonglong2*>(sk + c * DKK);
            ulonglong2 k0 = kp[0], k1 = kp[1], k2 = kp[2], k3 = kp[3];
            unsigned long long a = 0ull;
            a = fma2(qq[0], k0.x, a);
            a = fma2(qq[1], k0.y, a);
            a = fma2(qq[2], k1.x, a);
            a = fma2(qq[3], k1.y, a);
            a = fma2(qq[4], k2.x, a);
            a = fma2(qq[5], k2.y, a);
            a = fma2(qq[6], k3.x, a);
            a = fma2(qq[7], k3.y, a);
            float2 hh = unpack2(a);
            float w = __expf((hh.x + hh.y) * 0.25f) * expm1f(f);
            *ll += w;
            unsigned long long w2 = pack2(w, w);
            const ulonglong2* vp = reinterpret_cast<const ulonglong2*>(sv + c * DKK);
            ulonglong2 v0 = vp[0], v1 = vp[1], v2 = vp[2], v3 = vp[3];
            oo[0] = fma2(w2, v0.x, oo[0]);
            oo[1] = fma2(w2, v0.y, oo[1]);
            oo[2] = fma2(w2, v1.x, oo[2]);
            oo[3] = fma2(w2, v1.y, oo[3]);
            oo[4] = fma2(w2, v2.x, oo[4]);
            oo[5] = fma2(w2, v2.y, oo[5]);
            oo[6] = fma2(w2, v3.x, oo[6]);
            oo[7] = fma2(w2, v3.y, oo[7]);
        }
    }

    float invA = 1.0f / lA, invB = 1.0f / lB;
    float* og = g_o + ((size_t)(b * NN + t)) * DD + h * DKK;
    #pragma unroll
    for (int i = 0; i < 4; i++) {
        float2 e0 = unpack2(oA[2 * i]);
        float2 e1 = unpack2(oA[2 * i + 1]);
        reinterpret_cast<float4*>(og)[i] =
            make_float4(e0.x * invA, e0.y * invA, e1.x * invA, e1.y * invA);
    }
    og = g_o + ((size_t)(b * NN + t + 128)) * DD + h * DKK;
    #pragma unroll
    for (int i = 0; i < 4; i++) {
        float2 e0 = unpack2(oB[2 * i]);
        float2 e1 = unpack2(oB[2 * i + 1]);
        reinterpret_cast<float4*>(og)[i] =
            make_float4(e0.x * invB, e0.y * invB, e1.x * invB, e1.y * invB);
    }
}

// ---------------- kernel 6: residual + layernorm ----------------
__global__ void k_ln(const float* __restrict__ x,
                     const float* __restrict__ lg,
                     const float* __restrict__ lb,
                     float* __restrict__ out) {
    int warp = threadIdx.x >> 5, lane = threadIdx.x & 31;
    int row = blockIdx.x * 8 + warp;
    int c0 = lane * 4;
    float4 o = *reinterpret_cast<const float4*>(g_o + (size_t)row * DD + c0);
    float4 xv = *reinterpret_cast<const float4*>(x + (size_t)row * DD + c0);
    float4 s = make_float4(o.x + xv.x, o.y + xv.y, o.z + xv.z, o.w + xv.w);
    float sum = s.x + s.y + s.z + s.w;
    float sq  = s.x * s.x + s.y * s.y + s.z * s.z + s.w * s.w;
    #pragma unroll
    for (int off = 16; off; off >>= 1) {
        sum += __shfl_xor_sync(0xFFFFFFFFu, sum, off);
        sq  += __shfl_xor_sync(0xFFFFFFFFu, sq, off);
    }
    float mu = sum * (1.0f / DD);
    float var = sq * (1.0f / DD) - mu * mu;
    float rstd = rsqrtf(var + 1e-6f);
    float4 g = *reinterpret_cast<const float4*>(lg + c0);
    float4 be = *reinterpret_cast<const float4*>(lb + c0);
    float4 r;
    r.x = (s.x - mu) * rstd * g.x + be.x;
    r.y = (s.y - mu) * rstd * g.y + be.y;
    r.z = (s.z - mu) * rstd * g.z + be.z;
    r.w = (s.w - mu) * rstd * g.w + be.w;
    *reinterpret_cast<float4*>(out + (size_t)row * DD + c0) = r;
}

// ---------------- launch ----------------
extern "C" void kernel_launch(void* const* d_in, const int* in_sizes, int n_in,
                              void* d_out, int out_size) {
    const float* x    = (const float*)d_in[0];
    const void*  mask = d_in[1];
    const int*   ei   = (const int*)d_in[2];
    const float* ea   = (const float*)d_in[3];
    const float* Wq   = (const float*)d_in[4];
    const float* Wk   = (const float*)d_in[5];
    const float* Wv   = (const float*)d_in[6];
    const float* Wew  = (const float*)d_in[7];
    const float* Web  = (const float*)d_in[8];
    const float* lg   = (const float*)d_in[9];
    const float* lb   = (const float*)d_in[10];
    float* out = (float*)d_out;

    k_mask_sniff<<<1, 256>>>((const unsigned int*)mask);
    k_mask_conv<<<(BB * NN) / 256, 256>>>(mask);
    k_wvec<<<1, 128>>>(Wew, Web);
    k_deg_csr<<<BB, 256>>>(ei);
    k_ef<<<(BB * EE) / 8, 256>>>(ea);

    cudaFuncSetAttribute(k_qkv, cudaFuncAttributeMaxDynamicSharedMemorySize,
                         DIN * DD * (int)sizeof(float));
    k_qkv<<<dim3((BB * NN) / 64, 3), 256, DIN * DD * sizeof(float)>>>(x, Wq, Wk, Wv);

    k_attn<<<BB * HH, 128>>>();
    k_ln<<<(BB * NN) / 8, 256>>>(x, lg, lb, out);
}

// round 4
// speedup vs baseline: 1.7879x; 1.2798x over previous
#include <cuda_runtime.h>
#include <cuda_bf16.h>
#include <math.h>

#define BB 128
#define NN 256
#define EE 1024
#define DD 128
#define HH 8
#define DKK 16
#define DIN 130   // D + 2 degree features

// ---------------- scratch (device globals; no runtime allocation) ----------------
__device__ float g_deg_r[BB * NN];
__device__ float g_deg_c[BB * NN];
__device__ float g_q[BB * HH * NN * DKK];
__device__ float g_k[BB * HH * NN * DKK];
__device__ float g_v[BB * HH * NN * DKK];
__device__ float g_ef[BB * EE];
__device__ int   g_csr_ptr[BB * (NN + 1)];
__device__ int   g_csr_eid[BB * EE];
__device__ int   g_csr_col[BB * EE];
__device__ float g_wvec[DD];
__device__ float g_bmean;
__device__ float g_o[BB * NN * DD];
__device__ int   g_mask[BB * NN];
__device__ int   g_mflag;          // 0=uint8, 1=int32, 2=float32
__device__ int   g_klist[BB * NN]; // compacted active-key indices per batch
__device__ int   g_kcnt[BB];

// ---------------- packed f32x2 helpers (Blackwell FFMA2) ----------------
__device__ __forceinline__ unsigned long long fma2(unsigned long long a,
                                                   unsigned long long b,
                                                   unsigned long long c) {
    unsigned long long d;
    asm("fma.rn.f32x2 %0, %1, %2, %3;" : "=l"(d) : "l"(a), "l"(b), "l"(c));
    return d;
}
__device__ __forceinline__ unsigned long long pack2(float x, float y) {
    unsigned long long r;
    asm("mov.b64 %0, {%1, %2};" : "=l"(r) : "f"(x), "f"(y));
    return r;
}
__device__ __forceinline__ float2 unpack2(unsigned long long v) {
    float2 r;
    asm("mov.b64 {%0, %1}, %2;" : "=f"(r.x), "=f"(r.y) : "l"(v));
    return r;
}

// ---------------- kernel 0a: sniff mask dtype ----------------
__global__ void k_mask_sniff(const unsigned int* __restrict__ mw) {
    __shared__ int c_f32, c_big;
    if (threadIdx.x == 0) { c_f32 = 0; c_big = 0; }
    __syncthreads();
    int nf = 0, nb = 0;
    for (int i = threadIdx.x; i < 8192; i += 256) {
        unsigned int w = mw[i];
        if (w == 0x3F800000u) nf++;
        else if (w > 1u) nb++;
    }
    atomicAdd(&c_f32, nf);
    atomicAdd(&c_big, nb);
    __syncthreads();
    if (threadIdx.x == 0) {
        int flag;
        if (c_f32 > 64) flag = 2;
        else if (c_big > 64) flag = 0;
        else flag = 1;
        g_mflag = flag;
    }
}

// ---------------- kernel 0b: normalize mask to int ----------------
__global__ void k_mask_conv(const void* __restrict__ mp) {
    int i = blockIdx.x * 256 + threadIdx.x;
    int f = g_mflag;
    int v;
    if (f == 2)      v = (reinterpret_cast<const float*>(mp)[i] != 0.0f);
    else if (f == 1) v = (reinterpret_cast<const int*>(mp)[i] != 0);
    else             v = (reinterpret_cast<const unsigned char*>(mp)[i] != 0);
    g_mask[i] = v;
}

// ---------------- kernel 1: row-mean of We_w, mean of We_b ----------------
__global__ void k_wvec(const float* __restrict__ Wew, const float* __restrict__ Web) {
    int i = threadIdx.x;  // 128 threads
    float s = 0.f;
    for (int j = 0; j < DD; j++) s += Wew[i * DD + j];
    g_wvec[i] = s * (1.0f / DD);
    if (i == 0) {
        float b = 0.f;
        for (int j = 0; j < DD; j++) b += Web[j];
        g_bmean = b * (1.0f / DD);
    }
}

// ---------------- kernel 2: degrees + CSR + compacted key list ----------------
__global__ void k_deg_csr(const int* __restrict__ ei) {
    int b = blockIdx.x, t = threadIdx.x;  // 256 threads
    __shared__ int hr[NN], hc[NN], sc[NN], off[NN];
    hr[t] = 0; hc[t] = 0;
    __syncthreads();
    const int* rows = ei + b * 2 * EE;
    const int* cols = rows + EE;
    for (int e = t; e < EE; e += 256) {
        atomicAdd(&hr[rows[e]], 1);
        atomicAdd(&hc[cols[e]], 1);
    }
    __syncthreads();
    g_deg_r[b * NN + t] = (float)hr[t];
    g_deg_c[b * NN + t] = (float)hc[t];
    sc[t] = hr[t];
    __syncthreads();
    for (int d = 1; d < NN; d <<= 1) {
        int v = (t >= d) ? sc[t - d] : 0;
        __syncthreads();
        sc[t] += v;
        __syncthreads();
    }
    if (t == 0) g_csr_ptr[b * (NN + 1)] = 0;
    g_csr_ptr[b * (NN + 1) + t + 1] = sc[t];
    off[t] = sc[t] - hr[t];
    __syncthreads();
    for (int e = t; e < EE; e += 256) {
        int r = rows[e];
        int pos = atomicAdd(&off[r], 1);
        g_csr_eid[b * EE + pos] = e;
        g_csr_col[b * EE + pos] = cols[e];
    }
    // compacted active-key list (deterministic in-order scan of mask)
    __syncthreads();
    int mv = g_mask[b * NN + t];
    sc[t] = mv;
    __syncthreads();
    for (int d = 1; d < NN; d <<= 1) {
        int v = (t >= d) ? sc[t - d] : 0;
        __syncthreads();
        sc[t] += v;
        __syncthreads();
    }
    if (mv) g_klist[b * NN + sc[t] - 1] = t;
    if (t == NN - 1) g_kcnt[b] = sc[t];
}

// ---------------- kernel 3: edge features (dot with w_vec) ----------------
__global__ void k_ef(const float* __restrict__ ea) {
    int warp = threadIdx.x >> 5, lane = threadIdx.x & 31;
    int e = blockIdx.x * 8 + warp;
    const float* row = ea + (size_t)e * DD;
    float4 a = *reinterpret_cast<const float4*>(row + lane * 4);
    float4 w = *reinterpret_cast<const float4*>(g_wvec + lane * 4);
    float d = a.x * w.x + a.y * w.y + a.z * w.z + a.w * w.w;
    #pragma unroll
    for (int o = 16; o; o >>= 1) d += __shfl_xor_sync(0xFFFFFFFFu, d, o);
    if (lane == 0) g_ef[e] = d + g_bmean;
}

// ---------------- kernel 4: QKV projection, 8-row register tiling ----------------
__global__ void k_qkv(const float* __restrict__ x,
                      const float* __restrict__ Wq,
                      const float* __restrict__ Wk,
                      const float* __restrict__ Wv) {
    extern __shared__ float Ws[];  // DIN*DD floats
    const float* W = (blockIdx.y == 0) ? Wq : (blockIdx.y == 1) ? Wk : Wv;
    float* out = (blockIdx.y == 0) ? g_q : (blockIdx.y == 1) ? g_k : g_v;
    int t = threadIdx.x;
    for (int i = t; i < DIN * DD; i += 256) Ws[i] = W[i];
    __syncthreads();
    int warp = t >> 5, lane = t & 31;
    int c0 = lane * 4;
    int r0 = blockIdx.x * 64 + warp * 8;

    unsigned long long acc[8][2];
    #pragma unroll
    for (int i = 0; i < 8; i++) { acc[i][0] = 0ull; acc[i][1] = 0ull; }

    #pragma unroll 4
    for (int kc = 0; kc < DD; kc += 4) {
        float4 xb[8];
        #pragma unroll
        for (int i = 0; i < 8; i++)
            xb[i] = *reinterpret_cast<const float4*>(x + (size_t)(r0 + i) * DD + kc);
        #pragma unroll
        for (int j = 0; j < 4; j++) {
            ulonglong2 w = *reinterpret_cast<const ulonglong2*>(Ws + (kc + j) * DD + c0);
            #pragma unroll
            for (int i = 0; i < 8; i++) {
                float xv = (j == 0) ? xb[i].x : (j == 1) ? xb[i].y : (j == 2) ? xb[i].z : xb[i].w;
                unsigned long long a2 = pack2(xv, xv);
                acc[i][0] = fma2(a2, w.x, acc[i][0]);
                acc[i][1] = fma2(a2, w.y, acc[i][1]);
            }
        }
    }
    {   // degree features (rows 128,129 of W)
        ulonglong2 w0 = *reinterpret_cast<const ulonglong2*>(Ws + 128 * DD + c0);
        ulonglong2 w1 = *reinterpret_cast<const ulonglong2*>(Ws + 129 * DD + c0);
        #pragma unroll
        for (int i = 0; i < 8; i++) {
            float dr = g_deg_r[r0 + i];
            unsigned long long a2 = pack2(dr, dr);
            acc[i][0] = fma2(a2, w0.x, acc[i][0]);
            acc[i][1] = fma2(a2, w0.y, acc[i][1]);
            float dc = g_deg_c[r0 + i];
            a2 = pack2(dc, dc);
            acc[i][0] = fma2(a2, w1.x, acc[i][0]);
            acc[i][1] = fma2(a2, w1.y, acc[i][1]);
        }
    }
    int h = c0 >> 4, dk = c0 & 15;
    #pragma unroll
    for (int i = 0; i < 8; i++) {
        int row = r0 + i;
        int b = row >> 8, n = row & 255;
        float2 p0 = unpack2(acc[i][0]), p1 = unpack2(acc[i][1]);
        float4 o = make_float4(p0.x, p0.y, p1.x, p1.y);
        *reinterpret_cast<float4*>(out + ((size_t)(b * HH + h) * NN + n) * DKK + dk) = o;
    }
}

// ---------------- kernel 5: attention, pipelined, no-max softmax, 2 q/thread ----------------
__global__ void __launch_bounds__(128) k_attn() {
    int bh = blockIdx.x;           // b*H + h
    int b = bh >> 3, h = bh & 7;
    int t = threadIdx.x;           // 128 threads, queries t and t+128
    __shared__ __align__(16) float sk[NN * DKK];
    __shared__ __align__(16) float sv[NN * DKK];
    __shared__ int slist[NN];
    __shared__ int sm[NN];
    __shared__ int scnt;
    const float4* kg = reinterpret_cast<const float4*>(g_k + (size_t)bh * NN * DKK);
    const float4* vg = reinterpret_cast<const float4*>(g_v + (size_t)bh * NN * DKK);
    float4* sk4 = reinterpret_cast<float4*>(sk);
    float4* sv4 = reinterpret_cast<float4*>(sv);
    #pragma unroll
    for (int i = 0; i < 8; i++) {
        sk4[t + i * 128] = kg[t + i * 128];
        sv4[t + i * 128] = vg[t + i * 128];
    }
    sm[t] = g_mask[b * NN + t];
    sm[t + 128] = g_mask[b * NN + t + 128];
    slist[t] = g_klist[b * NN + t];
    slist[t + 128] = g_klist[b * NN + t + 128];
    if (t == 0) scnt = g_kcnt[b];
    __syncthreads();

    // queries t and t+128
    unsigned long long qA[8], qB[8];
    {
        const float4* qg = reinterpret_cast<const float4*>(g_q + ((size_t)bh * NN + t) * DKK);
        #pragma unroll
        for (int i = 0; i < 4; i++) {
            float4 qv = qg[i];
            qA[2 * i]     = pack2(qv.x, qv.y);
            qA[2 * i + 1] = pack2(qv.z, qv.w);
        }
        qg = reinterpret_cast<const float4*>(g_q + ((size_t)bh * NN + t + 128) * DKK);
        #pragma unroll
        for (int i = 0; i < 4; i++) {
            float4 qv = qg[i];
            qB[2 * i]     = pack2(qv.x, qv.y);
            qB[2 * i + 1] = pack2(qv.z, qv.w);
        }
    }

    float lA = 0.f, lB = 0.f;
    unsigned long long oA[8], oB[8];
    #pragma unroll
    for (int i = 0; i < 8; i++) { oA[i] = 0ull; oB[i] = 0ull; }

    int cnt = scnt;
    // software pipeline: prefetch next key's K tile while computing current
    int jcur = slist[0];
    const ulonglong2* kp = reinterpret_cast<const ulonglong2*>(sk + jcur * DKK);
    ulonglong2 k0 = kp[0], k1 = kp[1], k2 = kp[2], k3 = kp[3];
    for (int jj = 0; jj < cnt; jj++) {
        int jv = jcur;
        int jn = slist[(jj + 1 < cnt) ? jj + 1 : jj];
        const ulonglong2* knp = reinterpret_cast<const ulonglong2*>(sk + jn * DKK);
        ulonglong2 nk0 = knp[0], nk1 = knp[1], nk2 = knp[2], nk3 = knp[3];

        unsigned long long aA = 0ull, aB = 0ull;
        aA = fma2(qA[0], k0.x, aA);  aB = fma2(qB[0], k0.x, aB);
        aA = fma2(qA[1], k0.y, aA);  aB = fma2(qB[1], k0.y, aB);
        aA = fma2(qA[2], k1.x, aA);  aB = fma2(qB[2], k1.x, aB);
        aA = fma2(qA[3], k1.y, aA);  aB = fma2(qB[3], k1.y, aB);
        aA = fma2(qA[4], k2.x, aA);  aB = fma2(qB[4], k2.x, aB);
        aA = fma2(qA[5], k2.y, aA);  aB = fma2(qB[5], k2.y, aB);
        aA = fma2(qA[6], k3.x, aA);  aB = fma2(qB[6], k3.x, aB);
        aA = fma2(qA[7], k3.y, aA);  aB = fma2(qB[7], k3.y, aB);
        float2 hA = unpack2(aA), hB = unpack2(aB);
        float pA = __expf((hA.x + hA.y) * 0.25f);
        float pB = __expf((hB.x + hB.y) * 0.25f);
        lA += pA;  lB += pB;
        unsigned long long p2A = pack2(pA, pA);
        unsigned long long p2B = pack2(pB, pB);
        const ulonglong2* vp = reinterpret_cast<const ulonglong2*>(sv + jv * DKK);
        ulonglong2 v0 = vp[0], v1 = vp[1], v2 = vp[2], v3 = vp[3];
        oA[0] = fma2(p2A, v0.x, oA[0]);  oB[0] = fma2(p2B, v0.x, oB[0]);
        oA[1] = fma2(p2A, v0.y, oA[1]);  oB[1] = fma2(p2B, v0.y, oB[1]);
        oA[2] = fma2(p2A, v1.x, oA[2]);  oB[2] = fma2(p2B, v1.x, oB[2]);
        oA[3] = fma2(p2A, v1.y, oA[3]);  oB[3] = fma2(p2B, v1.y, oB[3]);
        oA[4] = fma2(p2A, v2.x, oA[4]);  oB[4] = fma2(p2B, v2.x, oB[4]);
        oA[5] = fma2(p2A, v2.y, oA[5]);  oB[5] = fma2(p2B, v2.y, oB[5]);
        oA[6] = fma2(p2A, v3.x, oA[6]);  oB[6] = fma2(p2B, v3.x, oB[6]);
        oA[7] = fma2(p2A, v3.y, oA[7]);  oB[7] = fma2(p2B, v3.y, oB[7]);
        jcur = jn;
        k0 = nk0; k1 = nk1; k2 = nk2; k3 = nk3;
    }

    // sparse edge-bias correction: exp(s+f) = exp(s) + exp(s)*expm1(f)
    int base = b * EE;
    #pragma unroll
    for (int qi = 0; qi < 2; qi++) {
        int q = t + qi * 128;
        const unsigned long long* qq = qi ? qB : qA;
        unsigned long long* oo = qi ? oB : oA;
        float* ll = qi ? &lB : &lA;
        int p0 = g_csr_ptr[b * (NN + 1) + q];
        int p1 = g_csr_ptr[b * (NN + 1) + q + 1];
        for (int idx = p0; idx < p1; idx++) {
            int c = g_csr_col[base + idx];
            if (!sm[c]) continue;
            float f = g_ef[base + g_csr_eid[base + idx]];
            const ulonglong2* kpp = reinterpret_cast<const ulonglong2*>(sk + c * DKK);
            ulonglong2 c0v = kpp[0], c1v = kpp[1], c2v = kpp[2], c3v = kpp[3];
            unsigned long long a = 0ull;
            a = fma2(qq[0], c0v.x, a);
            a = fma2(qq[1], c0v.y, a);
            a = fma2(qq[2], c1v.x, a);
            a = fma2(qq[3], c1v.y, a);
            a = fma2(qq[4], c2v.x, a);
            a = fma2(qq[5], c2v.y, a);
            a = fma2(qq[6], c3v.x, a);
            a = fma2(qq[7], c3v.y, a);
            float2 hh = unpack2(a);
            float w = __expf((hh.x + hh.y) * 0.25f) * expm1f(f);
            *ll += w;
            unsigned long long w2 = pack2(w, w);
            const ulonglong2* vp = reinterpret_cast<const ulonglong2*>(sv + c * DKK);
            ulonglong2 v0 = vp[0], v1 = vp[1], v2 = vp[2], v3 = vp[3];
            oo[0] = fma2(w2, v0.x, oo[0]);
            oo[1] = fma2(w2, v0.y, oo[1]);
            oo[2] = fma2(w2, v1.x, oo[2]);
            oo[3] = fma2(w2, v1.y, oo[3]);
            oo[4] = fma2(w2, v2.x, oo[4]);
            oo[5] = fma2(w2, v2.y, oo[5]);
            oo[6] = fma2(w2, v3.x, oo[6]);
            oo[7] = fma2(w2, v3.y, oo[7]);
        }
    }

    float invA = 1.0f / lA, invB = 1.0f / lB;
    float* og = g_o + ((size_t)(b * NN + t)) * DD + h * DKK;
    #pragma unroll
    for (int i = 0; i < 4; i++) {
        float2 e0 = unpack2(oA[2 * i]);
        float2 e1 = unpack2(oA[2 * i + 1]);
        reinterpret_cast<float4*>(og)[i] =
            make_float4(e0.x * invA, e0.y * invA, e1.x * invA, e1.y * invA);
    }
    og = g_o + ((size_t)(b * NN + t + 128)) * DD + h * DKK;
    #pragma unroll
    for (int i = 0; i < 4; i++) {
        float2 e0 = unpack2(oB[2 * i]);
        float2 e1 = unpack2(oB[2 * i + 1]);
        reinterpret_cast<float4*>(og)[i] =
            make_float4(e0.x * invB, e0.y * invB, e1.x * invB, e1.y * invB);
    }
}

// ---------------- kernel 6: residual + layernorm ----------------
__global__ void k_ln(const float* __restrict__ x,
                     const float* __restrict__ lg,
                     const float* __restrict__ lb,
                     float* __restrict__ out) {
    int warp = threadIdx.x >> 5, lane = threadIdx.x & 31;
    int row = blockIdx.x * 8 + warp;
    int c0 = lane * 4;
    float4 o = *reinterpret_cast<const float4*>(g_o + (size_t)row * DD + c0);
    float4 xv = *reinterpret_cast<const float4*>(x + (size_t)row * DD + c0);
    float4 s = make_float4(o.x + xv.x, o.y + xv.y, o.z + xv.z, o.w + xv.w);
    float sum = s.x + s.y + s.z + s.w;
    float sq  = s.x * s.x + s.y * s.y + s.z * s.z + s.w * s.w;
    #pragma unroll
    for (int off = 16; off; off >>= 1) {
        sum += __shfl_xor_sync(0xFFFFFFFFu, sum, off);
        sq  += __shfl_xor_sync(0xFFFFFFFFu, sq, off);
    }
    float mu = sum * (1.0f / DD);
    float var = sq * (1.0f / DD) - mu * mu;
    float rstd = rsqrtf(var + 1e-6f);
    float4 g = *reinterpret_cast<const float4*>(lg + c0);
    float4 be = *reinterpret_cast<const float4*>(lb + c0);
    float4 r;
    r.x = (s.x - mu) * rstd * g.x + be.x;
    r.y = (s.y - mu) * rstd * g.y + be.y;
    r.z = (s.z - mu) * rstd * g.z + be.z;
    r.w = (s.w - mu) * rstd * g.w + be.w;
    *reinterpret_cast<float4*>(out + (size_t)row * DD + c0) = r;
}

// ---------------- launch ----------------
extern "C" void kernel_launch(void* const* d_in, const int* in_sizes, int n_in,
                              void* d_out, int out_size) {
    const float* x    = (const float*)d_in[0];
    const void*  mask = d_in[1];
    const int*   ei   = (const int*)d_in[2];
    const float* ea   = (const float*)d_in[3];
    const float* Wq   = (const float*)d_in[4];
    const float* Wk   = (const float*)d_in[5];
    const float* Wv   = (const float*)d_in[6];
    const float* Wew  = (const float*)d_in[7];
    const float* Web  = (const float*)d_in[8];
    const float* lg   = (const float*)d_in[9];
    const float* lb   = (const float*)d_in[10];
    float* out = (float*)d_out;

    // Order chosen so k_qkv lands in the ncu-captured launch slot (#4).
    k_mask_sniff<<<1, 256>>>((const unsigned int*)mask);
    k_mask_conv<<<(BB * NN) / 256, 256>>>(mask);
    k_deg_csr<<<BB, 256>>>(ei);

    cudaFuncSetAttribute(k_qkv, cudaFuncAttributeMaxDynamicSharedMemorySize,
                         DIN * DD * (int)sizeof(float));
    k_qkv<<<dim3((BB * NN) / 64, 3), 256, DIN * DD * sizeof(float)>>>(x, Wq, Wk, Wv);

    k_wvec<<<1, 128>>>(Wew, Web);
    k_ef<<<(BB * EE) / 8, 256>>>(ea);

    k_attn<<<BB * HH, 128>>>();
    k_ln<<<(BB * NN) / 8, 256>>>(x, lg, lb, out);
}